// round 1
// baseline (speedup 1.0000x reference)
#include <cuda_runtime.h>
#include <math.h>

// ---------------------------------------------------------------------------
// Problem constants (B,3,256,448 inputs)
// ---------------------------------------------------------------------------
constexpr int BB = 4;
constexpr int HH = 256, WW = 448;
constexpr int HWF = HH * WW;                  // 114688
constexpr int H2 = 128, W2 = 224, HW2 = H2 * W2;  // 28672
constexpr int H4 = 64,  W4 = 112, HW4 = H4 * W4;  // 7168

constexpr long long N0 = (long long)BB * 6  * HWF;
constexpr long long N1 = (long long)BB * 64 * HWF;
constexpr long long N2 = (long long)BB * 128 * HW2;
constexpr long long N3 = (long long)BB * 192 * HW4;
constexpr long long N4 = (long long)BB * 2  * HWF;
constexpr long long SEC0 = 0;
constexpr long long SEC1 = SEC0 + N0;
constexpr long long SEC2 = SEC1 + N1;
constexpr long long SEC3 = SEC2 + N2;
constexpr long long SEC4 = SEC3 + N3;
constexpr long long NTOT = SEC4 + N4;         // 53,215,232 floats

constexpr long long DEN_F = 0;
constexpr long long DEN_H = 2LL * BB * HWF;            // after full-res dens
constexpr long long DEN_Q = DEN_H + 2LL * BB * HW2;
constexpr long long DEN_TOT = DEN_Q + 2LL * BB * HW4;  // 1,204,224 floats

// ---------------------------------------------------------------------------
// Device scratch (no allocations allowed -> __device__ globals)
// ---------------------------------------------------------------------------
__device__ __align__(16) float g_img0c[BB * 3 * HWF];
__device__ __align__(16) float g_img1c[BB * 3 * HWF];
__device__ __align__(16) float g_flow0t[BB * 2 * HWF];
__device__ __align__(16) float g_flow1t[BB * 2 * HWF];
__device__ __align__(16) float g_flowH[2][BB * 2 * HW2];
__device__ __align__(16) float g_flowQ[2][BB * 2 * HW4];
__device__ __align__(16) float g_mean[BB];
__device__ __align__(16) float g_bufA[BB * 32 * HWF];   // conv1 out
__device__ __align__(16) float g_f1[2][BB * 32 * HWF];  // conv2 out (kept)
__device__ __align__(16) float g_bufB[BB * 64 * HW2];   // conv3 out
__device__ __align__(16) float g_f2[2][BB * 64 * HW2];  // conv4 out (kept)
__device__ __align__(16) float g_bufC[BB * 96 * HW4];   // conv5 out
__device__ __align__(16) float g_f3[2][BB * 96 * HW4];  // conv6 out (kept)
__device__ __align__(16) float g_den[DEN_TOT];

// ---------------------------------------------------------------------------
// Utility kernels
// ---------------------------------------------------------------------------
__global__ void zero_kernel(float4* __restrict__ p, long long n4) {
    long long i = (long long)blockIdx.x * blockDim.x + threadIdx.x;
    if (i < n4) p[i] = make_float4(0.f, 0.f, 0.f, 0.f);
}

__global__ void mean_kernel(const float* __restrict__ img0,
                            const float* __restrict__ img1,
                            float* __restrict__ mn) {
    __shared__ float red[256];
    int b = blockIdx.x;
    const float* p0 = img0 + (size_t)b * 3 * HWF;
    const float* p1 = img1 + (size_t)b * 3 * HWF;
    float s = 0.f;
    for (int i = threadIdx.x; i < 3 * HWF; i += blockDim.x) s += p0[i] + p1[i];
    red[threadIdx.x] = s;
    __syncthreads();
    for (int k = blockDim.x / 2; k > 0; k >>= 1) {
        if (threadIdx.x < k) red[threadIdx.x] += red[threadIdx.x + k];
        __syncthreads();
    }
    if (threadIdx.x == 0) mn[b] = red[0] / (6.f * HWF);
}

__global__ void subtract_kernel(const float* __restrict__ img0,
                                const float* __restrict__ img1,
                                const float* __restrict__ mn,
                                float* __restrict__ o0, float* __restrict__ o1) {
    int id = blockIdx.x * blockDim.x + threadIdx.x;
    const int n = BB * 3 * HWF;
    if (id >= 2 * n) return;
    int sel = id >= n;
    int r = sel ? id - n : id;
    int b = r / (3 * HWF);
    float m = mn[b];
    if (sel) o1[r] = img1[r] - m;
    else     o0[r] = img0[r] - m;
}

// cal_inter_flow with t = 0.5 for both directions
__global__ void interflow_kernel(const float* __restrict__ flow01,
                                 const float* __restrict__ sig01,
                                 const float* __restrict__ flow10,
                                 const float* __restrict__ sig10,
                                 float* __restrict__ f0t, float* __restrict__ f1t) {
    int id = blockIdx.x * blockDim.x + threadIdx.x;
    const int n = 2 * BB * HWF;
    if (id >= n) return;
    int sel = id / (BB * HWF);
    int r = id - sel * (BB * HWF);
    int b = r / HWF;
    int p = r - b * HWF;
    const float* fl = sel ? flow10 : flow01;
    const float* sg = sel ? sig10 : sig01;
    float* dst = sel ? f1t : f0t;
    float fx = fl[((size_t)b * 2) * HWF + p];
    float fy = fl[((size_t)b * 2 + 1) * HWF + p];
    float s  = sg[(size_t)b * HWF + p];
    const float t = 0.5f;
    float ftx, fty;
    if (fabsf(s) < 0.01f) {
        ftx = t * fx;
        fty = t * fy;
    } else {
        float alpha = atan2f(fy, fx);
        float beta  = asinf(s);
        float d     = sqrtf(fx * fx + fy * fy);
        float R     = d / (2.f * s);
        const float PIH = 1.57079632679489662f;
        float th0 = alpha + PIH + beta;
        float th1 = alpha + PIH - beta;
        float tht = th0 + (th1 - th0) * t;
        ftx = R * (cosf(tht) - cosf(th0));
        fty = R * (sinf(tht) - sinf(th0));
    }
    dst[((size_t)b * 2) * HWF + p]     = ftx;
    dst[((size_t)b * 2 + 1) * HWF + p] = fty;
}

// jax.image.resize(method='bilinear', antialias=True) exact-factor downsample
// + flow magnitude scaling by 1/f (both channels since W/w == H/h == f).
__global__ void downflow_kernel(const float* __restrict__ fl, float* __restrict__ o,
                                int f, int ho, int wo) {
    const int hw = ho * wo;
    const int n = BB * 2 * hw;
    int id = blockIdx.x * blockDim.x + threadIdx.x;
    if (id >= n) return;
    int p = id % hw;
    int c = (id / hw) & 1;
    int b = id / (2 * hw);
    int oy = p / wo, ox = p % wo;
    float invf = 1.f / f;
    float sy = f * oy + (f - 1) * 0.5f;
    float sx = f * ox + (f - 1) * 0.5f;
    float wy[8], wxv[8];
    int jys[8], jxs[8];
    int ny = 0, nx = 0;
    float sumy = 0.f, sumx = 0.f;
    int jy0 = (int)floorf(sy) - f + 1;
    int jx0 = (int)floorf(sx) - f + 1;
    for (int k = 0; k < 2 * f; k++) {
        int jy = jy0 + k;
        float wv = 1.f - fabsf(jy - sy) * invf;
        if (jy >= 0 && jy < HH && wv > 0.f) { wy[ny] = wv; jys[ny] = jy; ny++; sumy += wv; }
        int jx = jx0 + k;
        wv = 1.f - fabsf(jx - sx) * invf;
        if (jx >= 0 && jx < WW && wv > 0.f) { wxv[nx] = wv; jxs[nx] = jx; nx++; sumx += wv; }
    }
    const float* ip = fl + ((size_t)b * 2 + c) * HWF;
    float acc = 0.f;
    for (int iy = 0; iy < ny; iy++) {
        const float* rp = ip + jys[iy] * WW;
        float rowacc = 0.f;
        for (int ix = 0; ix < nx; ix++) rowacc += wxv[ix] * rp[jxs[ix]];
        acc += wy[iy] * rowacc;
    }
    o[id] = acc / (sumy * sumx) * invf;
}

// ---------------------------------------------------------------------------
// Direct 3x3 conv + bias + PReLU. One thread = one output pixel x 32 cout.
// Input tile + weight chunk staged in smem; weights broadcast via LDS.128.
// ---------------------------------------------------------------------------
template<int CINC, int STRIDE, int TW, int TH>
__global__ __launch_bounds__(TW * TH)
void conv3x3_kernel(const float* __restrict__ in, const float* __restrict__ wgt,
                    const float* __restrict__ bias, const float* __restrict__ alpha,
                    float* __restrict__ out,
                    int Cin, int Cout, int Hin, int Win, int Hout, int Wout) {
    constexpr int IW = TW * STRIDE + 2;
    constexpr int IH = TH * STRIDE + 2;
    constexpr int NT = TW * TH;
    __shared__ __align__(16) float s_in[CINC * IH * IW];
    __shared__ __align__(16) float s_w[CINC * 9 * 32];

    const int tx = threadIdx.x, ty = threadIdx.y;
    const int tid = ty * TW + tx;
    const int nCo = Cout >> 5;
    const int b   = blockIdx.z / nCo;
    const int co0 = (blockIdx.z % nCo) << 5;
    const int ox0 = blockIdx.x * TW;
    const int oy0 = blockIdx.y * TH;
    const int ix0 = ox0 * STRIDE - 1;
    const int iy0 = oy0 * STRIDE - 1;

    const float* inB = in + (size_t)b * Cin * Hin * Win;

    float acc[32];
#pragma unroll
    for (int i = 0; i < 32; i++) acc[i] = 0.f;

    for (int cc = 0; cc < Cin; cc += CINC) {
        __syncthreads();
        for (int idx = tid; idx < CINC * IH * IW; idx += NT) {
            int ci = idx / (IH * IW);
            int r  = idx - ci * (IH * IW);
            int iy = r / IW;
            int ix = r - iy * IW;
            int gy = iy0 + iy, gx = ix0 + ix;
            float v = 0.f;
            if ((unsigned)gy < (unsigned)Hin && (unsigned)gx < (unsigned)Win)
                v = inB[((cc + ci) * Hin + gy) * Win + gx];
            s_in[idx] = v;
        }
        for (int idx = tid; idx < CINC * 9 * 32; idx += NT) {
            int co  = idx & 31;
            int rt  = idx >> 5;
            int ci  = rt / 9;
            int tap = rt - ci * 9;
            s_w[idx] = wgt[((co0 + co) * Cin + cc + ci) * 9 + tap];
        }
        __syncthreads();

        for (int ci = 0; ci < CINC; ci++) {
#pragma unroll
            for (int tap = 0; tap < 9; tap++) {
                const int ky = tap / 3, kx = tap % 3;
                float v = s_in[ci * IH * IW + (ty * STRIDE + ky) * IW + tx * STRIDE + kx];
                const float4* wp = reinterpret_cast<const float4*>(s_w + (ci * 9 + tap) * 32);
#pragma unroll
                for (int j = 0; j < 8; j++) {
                    float4 w4 = wp[j];
                    acc[4 * j + 0] = fmaf(v, w4.x, acc[4 * j + 0]);
                    acc[4 * j + 1] = fmaf(v, w4.y, acc[4 * j + 1]);
                    acc[4 * j + 2] = fmaf(v, w4.z, acc[4 * j + 2]);
                    acc[4 * j + 3] = fmaf(v, w4.w, acc[4 * j + 3]);
                }
            }
        }
    }

    const int ox = ox0 + tx, oy = oy0 + ty;
    if (ox < Wout && oy < Hout) {
        const float a = __ldg(alpha);
        float* ob = out + ((size_t)b * Cout + co0) * Hout * Wout + (size_t)oy * Wout + ox;
#pragma unroll
        for (int i = 0; i < 32; i++) {
            float r = acc[i] + __ldg(bias + co0 + i);
            r = r > 0.f ? r : a * r;
            ob[(size_t)i * Hout * Wout] = r;
        }
    }
}

// ---------------------------------------------------------------------------
// Forward-warp scatter: one thread per source pixel, loops channels,
// 4-corner bilinear splat via global atomics. den added once per image/scale.
// ---------------------------------------------------------------------------
__global__ void scatter_kernel(const float* __restrict__ src, int C,
                               const float* __restrict__ flow,
                               float* __restrict__ den,
                               float* __restrict__ outsec, int Ctot, int coff,
                               int Hs, int Ws) {
    const int HWs = Hs * Ws;
    int id = blockIdx.x * blockDim.x + threadIdx.x;
    if (id >= BB * HWs) return;
    int b = id / HWs;
    int p = id - b * HWs;
    int y = p / Ws;
    int x = p - y * Ws;
    const float* fb = flow + (size_t)b * 2 * HWs;
    float fx = fb[p], fy = fb[HWs + p];
    float txf = x + fx, tyf = y + fy;
    float x0f = floorf(txf), y0f = floorf(tyf);
    float dx = txf - x0f, dy = tyf - y0f;
    int x0 = (int)x0f, y0 = (int)y0f;
    float ws[4] = { (1.f - dx) * (1.f - dy), dx * (1.f - dy),
                    (1.f - dx) * dy,         dx * dy };
    int xs[4] = { x0, x0 + 1, x0, x0 + 1 };
    int ys[4] = { y0, y0, y0 + 1, y0 + 1 };
    int idxs[4];
    bool ok[4];
#pragma unroll
    for (int k = 0; k < 4; k++) {
        ok[k] = xs[k] >= 0 && xs[k] < Ws && ys[k] >= 0 && ys[k] < Hs && ws[k] > 0.f;
        idxs[k] = ys[k] * Ws + xs[k];
    }
    if (den) {
        float* dp = den + (size_t)b * HWs;
#pragma unroll
        for (int k = 0; k < 4; k++) if (ok[k]) atomicAdd(dp + idxs[k], ws[k]);
    }
    const float* sp = src + (size_t)b * C * HWs + p;
    float* op = outsec + ((size_t)b * Ctot + coff) * HWs;
    for (int c = 0; c < C; c++) {
        float v = sp[(size_t)c * HWs];
        float* oc = op + (size_t)c * HWs;
#pragma unroll
        for (int k = 0; k < 4; k++) if (ok[k]) atomicAdd(oc + idxs[k], v * ws[k]);
    }
}

__global__ void norm_kernel(float* __restrict__ sec, const float* __restrict__ den,
                            int Ctot, int Chalf, int HWs, long long n) {
    long long id = (long long)blockIdx.x * blockDim.x + threadIdx.x;
    if (id >= n) return;
    int p = (int)(id % HWs);
    long long t = id / HWs;
    int c = (int)(t % Ctot);
    int b = (int)(t / Ctot);
    int sel = (c >= Chalf) ? 1 : 0;
    float d = den[((size_t)sel * BB + b) * HWs + p];
    sec[id] = sec[id] / fmaxf(d, 1e-7f);
}

// ---------------------------------------------------------------------------
// Host launcher
// ---------------------------------------------------------------------------
static inline int div_up(long long a, int b) { return (int)((a + b - 1) / b); }

template<int CINC, int S, int TW, int TH>
static void launch_conv(const float* in, const float* w, const float* bi,
                        const float* al, float* out,
                        int Cin, int Cout, int Hin, int Win, int Hout, int Wout) {
    dim3 blk(TW, TH);
    dim3 grd((Wout + TW - 1) / TW, (Hout + TH - 1) / TH, BB * (Cout / 32));
    conv3x3_kernel<CINC, S, TW, TH><<<grd, blk>>>(in, w, bi, al, out,
                                                  Cin, Cout, Hin, Win, Hout, Wout);
}

extern "C" void kernel_launch(void* const* d_in, const int* in_sizes, int n_in,
                              void* d_out, int out_size) {
    const float* img0    = (const float*)d_in[0];
    const float* img1    = (const float*)d_in[1];
    const float* flow01  = (const float*)d_in[2];
    const float* sigma01 = (const float*)d_in[3];
    const float* flow10  = (const float*)d_in[4];
    const float* sigma10 = (const float*)d_in[5];
    const float *w[6], *bi[6], *al[6];
    for (int i = 0; i < 6; i++) {
        w[i]  = (const float*)d_in[6 + 3 * i];
        bi[i] = (const float*)d_in[7 + 3 * i];
        al[i] = (const float*)d_in[8 + 3 * i];
    }
    float* out = (float*)d_out;

    float *p_img0c, *p_img1c, *p_f0t, *p_f1t, *p_fH, *p_fQ, *p_mean;
    float *p_A, *p_f1, *p_B, *p_f2, *p_C, *p_f3, *p_den;
    cudaGetSymbolAddress((void**)&p_img0c, g_img0c);
    cudaGetSymbolAddress((void**)&p_img1c, g_img1c);
    cudaGetSymbolAddress((void**)&p_f0t,   g_flow0t);
    cudaGetSymbolAddress((void**)&p_f1t,   g_flow1t);
    cudaGetSymbolAddress((void**)&p_fH,    g_flowH);
    cudaGetSymbolAddress((void**)&p_fQ,    g_flowQ);
    cudaGetSymbolAddress((void**)&p_mean,  g_mean);
    cudaGetSymbolAddress((void**)&p_A,     g_bufA);
    cudaGetSymbolAddress((void**)&p_f1,    g_f1);
    cudaGetSymbolAddress((void**)&p_B,     g_bufB);
    cudaGetSymbolAddress((void**)&p_f2,    g_f2);
    cudaGetSymbolAddress((void**)&p_C,     g_bufC);
    cudaGetSymbolAddress((void**)&p_f3,    g_f3);
    cudaGetSymbolAddress((void**)&p_den,   g_den);

    // 1. zero output + den scratch
    zero_kernel<<<div_up(NTOT / 4, 256), 256>>>((float4*)out, NTOT / 4);
    zero_kernel<<<div_up(DEN_TOT / 4, 256), 256>>>((float4*)p_den, DEN_TOT / 4);

    // 2. mean-center images
    mean_kernel<<<BB, 256>>>(img0, img1, p_mean);
    subtract_kernel<<<div_up(2LL * BB * 3 * HWF, 256), 256>>>(img0, img1, p_mean,
                                                              p_img0c, p_img1c);

    // 3. intermediate flows (t = 0.5 both directions)
    interflow_kernel<<<div_up(2LL * BB * HWF, 256), 256>>>(flow01, sigma01,
                                                           flow10, sigma10,
                                                           p_f0t, p_f1t);

    // 4. antialiased downsampled flows (full-res flow == flow_0t identity)
    downflow_kernel<<<div_up((long long)BB * 2 * HW2, 256), 256>>>(p_f0t, p_fH, 2, H2, W2);
    downflow_kernel<<<div_up((long long)BB * 2 * HW2, 256), 256>>>(p_f1t, p_fH + (size_t)BB * 2 * HW2, 2, H2, W2);
    downflow_kernel<<<div_up((long long)BB * 2 * HW4, 256), 256>>>(p_f0t, p_fQ, 4, H4, W4);
    downflow_kernel<<<div_up((long long)BB * 2 * HW4, 256), 256>>>(p_f1t, p_fQ + (size_t)BB * 2 * HW4, 4, H4, W4);

    // 5. feature extractor for both images
    for (int sel = 0; sel < 2; sel++) {
        const float* imgc = sel ? p_img1c : p_img0c;
        float* f1s = p_f1 + (size_t)sel * BB * 32 * HWF;
        float* f2s = p_f2 + (size_t)sel * BB * 64 * HW2;
        float* f3s = p_f3 + (size_t)sel * BB * 96 * HW4;
        launch_conv<3, 1, 32, 8>(imgc, w[0], bi[0], al[0], p_A,  3,  32, HH, WW, HH, WW);
        launch_conv<8, 1, 32, 8>(p_A,  w[1], bi[1], al[1], f1s, 32, 32, HH, WW, HH, WW);
        launch_conv<8, 2, 16, 8>(f1s,  w[2], bi[2], al[2], p_B, 32, 64, HH, WW, H2, W2);
        launch_conv<8, 1, 32, 8>(p_B,  w[3], bi[3], al[3], f2s, 64, 64, H2, W2, H2, W2);
        launch_conv<8, 2, 16, 8>(f2s,  w[4], bi[4], al[4], p_C, 64, 96, H2, W2, H4, W4);
        launch_conv<8, 1, 16, 8>(p_C,  w[5], bi[5], al[5], f3s, 96, 96, H4, W4, H4, W4);
    }

    // 6. forward-warp scatters (den added once per image/scale via the feat call)
    for (int sel = 0; sel < 2; sel++) {
        const float* imgc  = sel ? p_img1c : p_img0c;
        const float* sig   = sel ? sigma10 : sigma01;
        const float* flF   = sel ? p_f1t   : p_f0t;
        const float* flH   = p_fH + (size_t)sel * BB * 2 * HW2;
        const float* flQ   = p_fQ + (size_t)sel * BB * 2 * HW4;
        const float* f1s = p_f1 + (size_t)sel * BB * 32 * HWF;
        const float* f2s = p_f2 + (size_t)sel * BB * 64 * HW2;
        const float* f3s = p_f3 + (size_t)sel * BB * 96 * HW4;
        float* denF = p_den + DEN_F + (size_t)sel * BB * HWF;
        float* denH = p_den + DEN_H + (size_t)sel * BB * HW2;
        float* denQ = p_den + DEN_Q + (size_t)sel * BB * HW4;

        int gF = div_up((long long)BB * HWF, 256);
        int gH = div_up((long long)BB * HW2, 256);
        int gQ = div_up((long long)BB * HW4, 256);
        scatter_kernel<<<gF, 256>>>(imgc, 3,  flF, nullptr, out + SEC0, 6,   3 * sel,  HH, WW);
        scatter_kernel<<<gF, 256>>>(f1s,  32, flF, denF,    out + SEC1, 64,  32 * sel, HH, WW);
        scatter_kernel<<<gF, 256>>>(sig,  1,  flF, nullptr, out + SEC4, 2,   sel,      HH, WW);
        scatter_kernel<<<gH, 256>>>(f2s,  64, flH, denH,    out + SEC2, 128, 64 * sel, H2, W2);
        scatter_kernel<<<gQ, 256>>>(f3s,  96, flQ, denQ,    out + SEC3, 192, 96 * sel, H4, W4);
    }

    // 7. normalize: out = num / max(den, 1e-7)
    norm_kernel<<<div_up(N0, 256), 256>>>(out + SEC0, p_den + DEN_F, 6,   3,  HWF, N0);
    norm_kernel<<<div_up(N1, 256), 256>>>(out + SEC1, p_den + DEN_F, 64,  32, HWF, N1);
    norm_kernel<<<div_up(N2, 256), 256>>>(out + SEC2, p_den + DEN_H, 128, 64, HW2, N2);
    norm_kernel<<<div_up(N3, 256), 256>>>(out + SEC3, p_den + DEN_Q, 192, 96, HW4, N3);
    norm_kernel<<<div_up(N4, 256), 256>>>(out + SEC4, p_den + DEN_F, 2,   1,  HWF, N4);
}

// round 2
// speedup vs baseline: 1.3529x; 1.3529x over previous
#include <cuda_runtime.h>
#include <math.h>

// ---------------------------------------------------------------------------
// Problem constants (B,3,256,448 inputs)
// ---------------------------------------------------------------------------
constexpr int BB = 4;
constexpr int HH = 256, WW = 448;
constexpr int HWF = HH * WW;                      // 114688
constexpr int H2 = 128, W2 = 224, HW2 = H2 * W2;  // 28672
constexpr int H4 = 64,  W4 = 112, HW4 = H4 * W4;  // 7168

constexpr long long N0 = (long long)BB * 6   * HWF;
constexpr long long N1 = (long long)BB * 64  * HWF;
constexpr long long N2 = (long long)BB * 128 * HW2;
constexpr long long N3 = (long long)BB * 192 * HW4;
constexpr long long N4 = (long long)BB * 2   * HWF;
constexpr long long SEC0 = 0;
constexpr long long SEC1 = SEC0 + N0;
constexpr long long SEC2 = SEC1 + N1;
constexpr long long SEC3 = SEC2 + N2;
constexpr long long SEC4 = SEC3 + N3;

// NHWC channel counts: src (warp source) and acc (splat accumulator, +den+pad)
constexpr int CF = 36, CFA = 40;   // full res:   [f1 32][img 3][sig 1] | +den
constexpr int CHh = 64, CHA = 68;  // half res:   f2                    | +den
constexpr int CQ = 96, CQA = 100;  // quarter:    f3                    | +den

// ---------------------------------------------------------------------------
// Device scratch (no allocations allowed -> __device__ globals)
// ---------------------------------------------------------------------------
__device__ __align__(16) float g_srcF[2][(size_t)BB * HWF * CF];
__device__ __align__(16) float g_accF[2][(size_t)BB * HWF * CFA];
__device__ __align__(16) float g_srcH[2][(size_t)BB * HW2 * CHh];
__device__ __align__(16) float g_accH[2][(size_t)BB * HW2 * CHA];
__device__ __align__(16) float g_srcQ[2][(size_t)BB * HW4 * CQ];
__device__ __align__(16) float g_accQ[2][(size_t)BB * HW4 * CQA];
__device__ __align__(16) float g_bufA[(size_t)BB * HWF * 32];
__device__ __align__(16) float g_bufB[(size_t)BB * HW2 * 64];
__device__ __align__(16) float g_bufC[(size_t)BB * HW4 * 96];
__device__ __align__(16) float g_flow0t[BB * 2 * HWF];
__device__ __align__(16) float g_flow1t[BB * 2 * HWF];
__device__ __align__(16) float g_flowH[2][BB * 2 * HW2];
__device__ __align__(16) float g_flowQ[2][BB * 2 * HW4];
__device__ __align__(16) float g_mean[BB];

// ---------------------------------------------------------------------------
// Packed fp32x2 helpers (sm_100 packed FMA path)
// ---------------------------------------------------------------------------
__device__ __forceinline__ unsigned long long pack2(float v) {
    unsigned long long r;
    asm("mov.b64 %0, {%1, %1};" : "=l"(r) : "r"(__float_as_uint(v)));
    return r;
}
__device__ __forceinline__ void ffma2(unsigned long long& d,
                                      unsigned long long a, unsigned long long b) {
    asm("fma.rn.f32x2 %0, %1, %2, %0;" : "+l"(d) : "l"(a), "l"(b));
}
__device__ __forceinline__ float2 unpack2(unsigned long long v) {
    float2 f;
    asm("mov.b64 {%0, %1}, %2;" : "=f"(f.x), "=f"(f.y) : "l"(v));
    return f;
}
__device__ __forceinline__ void red4(float* p, float a, float b, float c, float d) {
    asm volatile("red.global.add.v4.f32 [%0], {%1, %2, %3, %4};"
                 :: "l"(p), "f"(a), "f"(b), "f"(c), "f"(d) : "memory");
}

// ---------------------------------------------------------------------------
// Utility kernels
// ---------------------------------------------------------------------------
__global__ void zero_kernel(float4* __restrict__ p, long long n4) {
    long long i = (long long)blockIdx.x * blockDim.x + threadIdx.x;
    if (i < n4) p[i] = make_float4(0.f, 0.f, 0.f, 0.f);
}

__global__ void mean_kernel(const float* __restrict__ img0,
                            const float* __restrict__ img1,
                            float* __restrict__ mn) {
    __shared__ float red[256];
    int b = blockIdx.x;
    const float* p0 = img0 + (size_t)b * 3 * HWF;
    const float* p1 = img1 + (size_t)b * 3 * HWF;
    float s = 0.f;
    for (int i = threadIdx.x; i < 3 * HWF; i += blockDim.x) s += p0[i] + p1[i];
    red[threadIdx.x] = s;
    __syncthreads();
    for (int k = blockDim.x / 2; k > 0; k >>= 1) {
        if (threadIdx.x < k) red[threadIdx.x] += red[threadIdx.x + k];
        __syncthreads();
    }
    if (threadIdx.x == 0) mn[b] = red[0] / (6.f * HWF);
}

// mean-subtract images + sigma copy into srcF channels [32..35] (NHWC)
__global__ void prep_kernel(const float* __restrict__ img0,
                            const float* __restrict__ img1,
                            const float* __restrict__ sig01,
                            const float* __restrict__ sig10,
                            const float* __restrict__ mn,
                            float* __restrict__ srcF0, float* __restrict__ srcF1) {
    int id = blockIdx.x * blockDim.x + threadIdx.x;
    const int n = BB * HWF;
    if (id >= 2 * n) return;
    int sel = id >= n;
    int r = sel ? id - n : id;
    int b = r / HWF;
    int p = r - b * HWF;
    float m = mn[b];
    const float* im = sel ? img1 : img0;
    const float* sg = sel ? sig10 : sig01;
    float4 v;
    v.x = im[((size_t)b * 3 + 0) * HWF + p] - m;
    v.y = im[((size_t)b * 3 + 1) * HWF + p] - m;
    v.z = im[((size_t)b * 3 + 2) * HWF + p] - m;
    v.w = sg[(size_t)b * HWF + p];
    float* dst = (sel ? srcF1 : srcF0) + ((size_t)r) * CF + 32;
    *reinterpret_cast<float4*>(dst) = v;
}

// cal_inter_flow with t = 0.5 for both directions (planar NCHW flow out)
__global__ void interflow_kernel(const float* __restrict__ flow01,
                                 const float* __restrict__ sig01,
                                 const float* __restrict__ flow10,
                                 const float* __restrict__ sig10,
                                 float* __restrict__ f0t, float* __restrict__ f1t) {
    int id = blockIdx.x * blockDim.x + threadIdx.x;
    const int n = 2 * BB * HWF;
    if (id >= n) return;
    int sel = id / (BB * HWF);
    int r = id - sel * (BB * HWF);
    int b = r / HWF;
    int p = r - b * HWF;
    const float* fl = sel ? flow10 : flow01;
    const float* sg = sel ? sig10 : sig01;
    float* dst = sel ? f1t : f0t;
    float fx = fl[((size_t)b * 2) * HWF + p];
    float fy = fl[((size_t)b * 2 + 1) * HWF + p];
    float s  = sg[(size_t)b * HWF + p];
    const float t = 0.5f;
    float ftx, fty;
    if (fabsf(s) < 0.01f) {
        ftx = t * fx;
        fty = t * fy;
    } else {
        float alpha = atan2f(fy, fx);
        float beta  = asinf(s);
        float d     = sqrtf(fx * fx + fy * fy);
        float R     = d / (2.f * s);
        const float PIH = 1.57079632679489662f;
        float th0 = alpha + PIH + beta;
        float th1 = alpha + PIH - beta;
        float tht = th0 + (th1 - th0) * t;
        ftx = R * (cosf(tht) - cosf(th0));
        fty = R * (sinf(tht) - sinf(th0));
    }
    dst[((size_t)b * 2) * HWF + p]     = ftx;
    dst[((size_t)b * 2 + 1) * HWF + p] = fty;
}

// jax.image.resize(bilinear, antialias=True) exact-factor downsample + 1/f scale
__global__ void downflow_kernel(const float* __restrict__ fl, float* __restrict__ o,
                                int f, int ho, int wo) {
    const int hw = ho * wo;
    const int n = BB * 2 * hw;
    int id = blockIdx.x * blockDim.x + threadIdx.x;
    if (id >= n) return;
    int p = id % hw;
    int c = (id / hw) & 1;
    int b = id / (2 * hw);
    int oy = p / wo, ox = p % wo;
    float invf = 1.f / f;
    float sy = f * oy + (f - 1) * 0.5f;
    float sx = f * ox + (f - 1) * 0.5f;
    float wy[8], wxv[8];
    int jys[8], jxs[8];
    int ny = 0, nx = 0;
    float sumy = 0.f, sumx = 0.f;
    int jy0 = (int)floorf(sy) - f + 1;
    int jx0 = (int)floorf(sx) - f + 1;
    for (int k = 0; k < 2 * f; k++) {
        int jy = jy0 + k;
        float wv = 1.f - fabsf(jy - sy) * invf;
        if (jy >= 0 && jy < HH && wv > 0.f) { wy[ny] = wv; jys[ny] = jy; ny++; sumy += wv; }
        int jx = jx0 + k;
        wv = 1.f - fabsf(jx - sx) * invf;
        if (jx >= 0 && jx < WW && wv > 0.f) { wxv[nx] = wv; jxs[nx] = jx; nx++; sumx += wv; }
    }
    const float* ip = fl + ((size_t)b * 2 + c) * HWF;
    float acc = 0.f;
    for (int iy = 0; iy < ny; iy++) {
        const float* rp = ip + jys[iy] * WW;
        float rowacc = 0.f;
        for (int ix = 0; ix < nx; ix++) rowacc += wxv[ix] * rp[jxs[ix]];
        acc += wy[iy] * rowacc;
    }
    o[id] = acc / (sumy * sumx) * invf;
}

// ---------------------------------------------------------------------------
// 3x3 conv + bias + PReLU, NHWC in/out, packed f32x2 FMA, 2 pixels/thread.
// Each thread: 32 output channels x 2 pixels. smem input staged channel-planar.
// ---------------------------------------------------------------------------
template<int CINC, int STRIDE, int TW, int TH>
__global__ __launch_bounds__(TW * TH)
void conv3x3_kernel(const float* __restrict__ in, int CinStr, int Cin,
                    const float* __restrict__ wgt, const float* __restrict__ bias,
                    const float* __restrict__ alpha,
                    float* __restrict__ out, int CoutStr, int Cout,
                    int Hin, int Win, int Hout, int Wout) {
    constexpr int OW = 2 * TW;
    constexpr int IW = OW * STRIDE + 2;
    constexpr int IH = TH * STRIDE + 2;
    constexpr int NT = TW * TH;
    constexpr int IHW = IH * IW;
    __shared__ float s_in[CINC * IHW];
    __shared__ __align__(16) float s_w[CINC * 9 * 32];

    const int tx = threadIdx.x, ty = threadIdx.y;
    const int tid = ty * TW + tx;
    const int nCo = Cout >> 5;
    const int b   = blockIdx.z / nCo;
    const int co0 = (blockIdx.z % nCo) << 5;
    const int ox0 = blockIdx.x * OW;
    const int oy0 = blockIdx.y * TH;
    const int ix0 = ox0 * STRIDE - 1;
    const int iy0 = oy0 * STRIDE - 1;

    const float* inB = in + (size_t)b * Hin * Win * CinStr;

    unsigned long long a0[16], a1[16];
#pragma unroll
    for (int i = 0; i < 16; i++) { a0[i] = 0ull; a1[i] = 0ull; }

    for (int cc = 0; cc < Cin; cc += CINC) {
        __syncthreads();
        if constexpr (CINC % 4 == 0) {
            constexpr int Q = CINC / 4;
            for (int idx = tid; idx < IHW * Q; idx += NT) {
                int pix = idx / Q, q = idx - (idx / Q) * Q;
                int iy = pix / IW, ix = pix - iy * IW;
                int gy = iy0 + iy, gx = ix0 + ix;
                float4 v = make_float4(0.f, 0.f, 0.f, 0.f);
                if ((unsigned)gy < (unsigned)Hin && (unsigned)gx < (unsigned)Win)
                    v = *reinterpret_cast<const float4*>(
                        inB + ((size_t)gy * Win + gx) * CinStr + cc + 4 * q);
                s_in[(4 * q + 0) * IHW + pix] = v.x;
                s_in[(4 * q + 1) * IHW + pix] = v.y;
                s_in[(4 * q + 2) * IHW + pix] = v.z;
                s_in[(4 * q + 3) * IHW + pix] = v.w;
            }
        } else {
            for (int idx = tid; idx < CINC * IHW; idx += NT) {
                int ci = idx / IHW;
                int pix = idx - ci * IHW;
                int iy = pix / IW, ix = pix - iy * IW;
                int gy = iy0 + iy, gx = ix0 + ix;
                float v = 0.f;
                if ((unsigned)gy < (unsigned)Hin && (unsigned)gx < (unsigned)Win)
                    v = inB[((size_t)gy * Win + gx) * CinStr + cc + ci];
                s_in[idx] = v;
            }
        }
        for (int idx = tid; idx < CINC * 9 * 32; idx += NT) {
            int co  = idx & 31;
            int rt  = idx >> 5;
            int ci  = rt / 9;
            int tap = rt - ci * 9;
            s_w[(ci * 9 + tap) * 32 + co] =
                wgt[((size_t)(co0 + co) * Cin + cc + ci) * 9 + tap];
        }
        __syncthreads();

        for (int ci = 0; ci < CINC; ci++) {
            const float* bi = s_in + ci * IHW;
#pragma unroll
            for (int ky = 0; ky < 3; ky++) {
#pragma unroll
                for (int kx = 0; kx < 3; kx++) {
                    float v0 = bi[(ty * STRIDE + ky) * IW + tx * STRIDE + kx];
                    float v1 = bi[(ty * STRIDE + ky) * IW + (tx + TW) * STRIDE + kx];
                    unsigned long long vv0 = pack2(v0), vv1 = pack2(v1);
                    const ulonglong2* wp = reinterpret_cast<const ulonglong2*>(
                        s_w + (ci * 9 + ky * 3 + kx) * 32);
#pragma unroll
                    for (int j = 0; j < 8; j++) {
                        ulonglong2 w2 = wp[j];
                        ffma2(a0[2 * j],     vv0, w2.x);
                        ffma2(a0[2 * j + 1], vv0, w2.y);
                        ffma2(a1[2 * j],     vv1, w2.x);
                        ffma2(a1[2 * j + 1], vv1, w2.y);
                    }
                }
            }
        }
    }

    const float al = __ldg(alpha);
    const int oy = oy0 + ty;
#pragma unroll
    for (int px = 0; px < 2; px++) {
        const int ox = ox0 + tx + px * TW;
        if (ox < Wout && oy < Hout) {
            float* op = out + ((size_t)b * Hout * Wout + (size_t)oy * Wout + ox) * CoutStr + co0;
            const unsigned long long* ap = px ? a1 : a0;
#pragma unroll
            for (int j = 0; j < 8; j++) {
                float2 p0 = unpack2(ap[2 * j]);
                float2 p1 = unpack2(ap[2 * j + 1]);
                float4 o4;
                float r;
                r = p0.x + __ldg(bias + co0 + 4 * j + 0); o4.x = r > 0.f ? r : al * r;
                r = p0.y + __ldg(bias + co0 + 4 * j + 1); o4.y = r > 0.f ? r : al * r;
                r = p1.x + __ldg(bias + co0 + 4 * j + 2); o4.z = r > 0.f ? r : al * r;
                r = p1.y + __ldg(bias + co0 + 4 * j + 3); o4.w = r > 0.f ? r : al * r;
                reinterpret_cast<float4*>(op)[j] = o4;
            }
        }
    }
}

// ---------------------------------------------------------------------------
// Forward-warp scatter: NHWC src, NHWC acc (den at channel C), v4 reductions.
// ---------------------------------------------------------------------------
template<int C4, int CA>
__global__ void scatter_kernel(const float* __restrict__ src,
                               const float* __restrict__ flow,
                               float* __restrict__ acc, int Hs, int Ws) {
    constexpr int C = 4 * C4;
    const int HWs = Hs * Ws;
    int id = blockIdx.x * blockDim.x + threadIdx.x;
    if (id >= BB * HWs) return;
    int b = id / HWs;
    int p = id - b * HWs;
    int y = p / Ws;
    int x = p - y * Ws;
    const float* fb = flow + (size_t)b * 2 * HWs;
    float fx = fb[p], fy = fb[HWs + p];
    float txf = x + fx, tyf = y + fy;
    float x0f = floorf(txf), y0f = floorf(tyf);
    float dx = txf - x0f, dy = tyf - y0f;
    int x0 = (int)x0f, y0 = (int)y0f;
    float w[4] = { (1.f - dx) * (1.f - dy), dx * (1.f - dy),
                   (1.f - dx) * dy,         dx * dy };
    int xs[4] = { x0, x0 + 1, x0, x0 + 1 };
    int ys[4] = { y0, y0, y0 + 1, y0 + 1 };
    int idxs[4];
    bool ok[4];
#pragma unroll
    for (int k = 0; k < 4; k++) {
        ok[k] = xs[k] >= 0 && xs[k] < Ws && ys[k] >= 0 && ys[k] < Hs && w[k] > 0.f;
        idxs[k] = ys[k] * Ws + xs[k];
    }
    float* accB = acc + (size_t)b * HWs * CA;
    const float4* sp = reinterpret_cast<const float4*>(src + (size_t)id * C);
#pragma unroll
    for (int c4 = 0; c4 < C4; c4++) {
        float4 v = sp[c4];
#pragma unroll
        for (int k = 0; k < 4; k++) {
            if (ok[k])
                red4(accB + (size_t)idxs[k] * CA + 4 * c4,
                     v.x * w[k], v.y * w[k], v.z * w[k], v.w * w[k]);
        }
    }
#pragma unroll
    for (int k = 0; k < 4; k++)
        if (ok[k]) atomicAdd(accB + (size_t)idxs[k] * CA + C, w[k]);
}

// ---------------------------------------------------------------------------
// Finalize: NHWC acc -> divide by den -> NCHW output sections
// ---------------------------------------------------------------------------
template<int C, int CA>
__global__ void finalize_simple(const float* __restrict__ acc,
                                float* __restrict__ outsec,
                                int Ctot, int coff, int HWs) {
    __shared__ float s[64 * (CA + 1)];
    __shared__ float inv[64];
    const int base = blockIdx.x * 64;
    const int tid = threadIdx.x;
    constexpr int Q = CA / 4;
    for (int idx = tid; idx < 64 * Q; idx += 256) {
        int p = idx / Q, q = idx - (idx / Q) * Q;
        float4 v = *reinterpret_cast<const float4*>(acc + ((size_t)(base + p)) * CA + 4 * q);
        s[p * (CA + 1) + 4 * q + 0] = v.x;
        s[p * (CA + 1) + 4 * q + 1] = v.y;
        s[p * (CA + 1) + 4 * q + 2] = v.z;
        s[p * (CA + 1) + 4 * q + 3] = v.w;
    }
    __syncthreads();
    if (tid < 64) inv[tid] = 1.f / fmaxf(s[tid * (CA + 1) + C], 1e-7f);
    __syncthreads();
    const int b = base / HWs;
    const int p0 = base - b * HWs;
    for (int id = tid; id < C * 64; id += 256) {
        int c = id >> 6, i = id & 63;
        outsec[((size_t)(b * Ctot + coff + c)) * HWs + p0 + i] = s[i * (CA + 1) + c] * inv[i];
    }
}

// full-res: channels 0-31 -> SEC1(feat), 32-34 -> SEC0(img), 35 -> SEC4(sig)
__global__ void finalize_full(const float* __restrict__ acc,
                              float* __restrict__ out, int sel) {
    __shared__ float s[64 * 41];
    __shared__ float inv[64];
    const int base = blockIdx.x * 64;
    const int tid = threadIdx.x;
    for (int idx = tid; idx < 64 * 10; idx += 256) {
        int p = idx / 10, q = idx - (idx / 10) * 10;
        float4 v = *reinterpret_cast<const float4*>(acc + ((size_t)(base + p)) * CFA + 4 * q);
        s[p * 41 + 4 * q + 0] = v.x;
        s[p * 41 + 4 * q + 1] = v.y;
        s[p * 41 + 4 * q + 2] = v.z;
        s[p * 41 + 4 * q + 3] = v.w;
    }
    __syncthreads();
    if (tid < 64) inv[tid] = 1.f / fmaxf(s[tid * 41 + 36], 1e-7f);
    __syncthreads();
    const int b = base / HWF;
    const int p0 = base - b * HWF;
    for (int id = tid; id < 36 * 64; id += 256) {
        int c = id >> 6, i = id & 63;
        float val = s[i * 41 + c] * inv[i];
        size_t dst;
        if (c < 32)       dst = SEC1 + ((size_t)(b * 64 + 32 * sel + c)) * HWF + p0 + i;
        else if (c < 35)  dst = SEC0 + ((size_t)(b * 6 + 3 * sel + (c - 32))) * HWF + p0 + i;
        else              dst = SEC4 + ((size_t)(b * 2 + sel)) * HWF + p0 + i;
        out[dst] = val;
    }
}

// ---------------------------------------------------------------------------
// Host launcher
// ---------------------------------------------------------------------------
static inline int div_up(long long a, int b) { return (int)((a + b - 1) / b); }

extern "C" void kernel_launch(void* const* d_in, const int* in_sizes, int n_in,
                              void* d_out, int out_size) {
    const float* img0    = (const float*)d_in[0];
    const float* img1    = (const float*)d_in[1];
    const float* flow01  = (const float*)d_in[2];
    const float* sigma01 = (const float*)d_in[3];
    const float* flow10  = (const float*)d_in[4];
    const float* sigma10 = (const float*)d_in[5];
    const float *w[6], *bi[6], *al[6];
    for (int i = 0; i < 6; i++) {
        w[i]  = (const float*)d_in[6 + 3 * i];
        bi[i] = (const float*)d_in[7 + 3 * i];
        al[i] = (const float*)d_in[8 + 3 * i];
    }
    float* out = (float*)d_out;

    float *p_srcF, *p_accF, *p_srcH, *p_accH, *p_srcQ, *p_accQ;
    float *p_bufA, *p_bufB, *p_bufC, *p_f0t, *p_f1t, *p_fH, *p_fQ, *p_mean;
    cudaGetSymbolAddress((void**)&p_srcF, g_srcF);
    cudaGetSymbolAddress((void**)&p_accF, g_accF);
    cudaGetSymbolAddress((void**)&p_srcH, g_srcH);
    cudaGetSymbolAddress((void**)&p_accH, g_accH);
    cudaGetSymbolAddress((void**)&p_srcQ, g_srcQ);
    cudaGetSymbolAddress((void**)&p_accQ, g_accQ);
    cudaGetSymbolAddress((void**)&p_bufA, g_bufA);
    cudaGetSymbolAddress((void**)&p_bufB, g_bufB);
    cudaGetSymbolAddress((void**)&p_bufC, g_bufC);
    cudaGetSymbolAddress((void**)&p_f0t,  g_flow0t);
    cudaGetSymbolAddress((void**)&p_f1t,  g_flow1t);
    cudaGetSymbolAddress((void**)&p_fH,   g_flowH);
    cudaGetSymbolAddress((void**)&p_fQ,   g_flowQ);
    cudaGetSymbolAddress((void**)&p_mean, g_mean);

    const size_t szSF = (size_t)BB * HWF * CF;
    const size_t szAF = (size_t)BB * HWF * CFA;
    const size_t szSH = (size_t)BB * HW2 * CHh;
    const size_t szAH = (size_t)BB * HW2 * CHA;
    const size_t szSQ = (size_t)BB * HW4 * CQ;
    const size_t szAQ = (size_t)BB * HW4 * CQA;

    // 1. zero accumulators
    zero_kernel<<<div_up(2LL * szAF / 4, 256), 256>>>((float4*)p_accF, 2LL * szAF / 4);
    zero_kernel<<<div_up(2LL * szAH / 4, 256), 256>>>((float4*)p_accH, 2LL * szAH / 4);
    zero_kernel<<<div_up(2LL * szAQ / 4, 256), 256>>>((float4*)p_accQ, 2LL * szAQ / 4);

    // 2. mean-center images + pack img/sig into srcF ch 32..35
    mean_kernel<<<BB, 256>>>(img0, img1, p_mean);
    prep_kernel<<<div_up(2LL * BB * HWF, 256), 256>>>(img0, img1, sigma01, sigma10,
                                                      p_mean, p_srcF, p_srcF + szSF);

    // 3. intermediate flows (t = 0.5 both directions)
    interflow_kernel<<<div_up(2LL * BB * HWF, 256), 256>>>(flow01, sigma01,
                                                           flow10, sigma10,
                                                           p_f0t, p_f1t);

    // 4. antialiased downsampled flows
    downflow_kernel<<<div_up((long long)BB * 2 * HW2, 256), 256>>>(p_f0t, p_fH, 2, H2, W2);
    downflow_kernel<<<div_up((long long)BB * 2 * HW2, 256), 256>>>(p_f1t, p_fH + (size_t)BB * 2 * HW2, 2, H2, W2);
    downflow_kernel<<<div_up((long long)BB * 2 * HW4, 256), 256>>>(p_f0t, p_fQ, 4, H4, W4);
    downflow_kernel<<<div_up((long long)BB * 2 * HW4, 256), 256>>>(p_f1t, p_fQ + (size_t)BB * 2 * HW4, 4, H4, W4);

    // 5. feature extractor (NHWC), both images
    for (int sel = 0; sel < 2; sel++) {
        float* srcF = p_srcF + (size_t)sel * szSF;
        float* srcH = p_srcH + (size_t)sel * szSH;
        float* srcQ = p_srcQ + (size_t)sel * szSQ;
        // conv1: img(3, stride36 @ch32) -> bufA(32)
        conv3x3_kernel<3, 1, 32, 4><<<dim3(7, 64, BB), dim3(32, 4)>>>(
            srcF + 32, CF, 3, w[0], bi[0], al[0], p_bufA, 32, 32, HH, WW, HH, WW);
        // conv2: bufA(32) -> srcF ch0..31 (stride 36)
        conv3x3_kernel<8, 1, 32, 4><<<dim3(7, 64, BB), dim3(32, 4)>>>(
            p_bufA, 32, 32, w[1], bi[1], al[1], srcF, CF, 32, HH, WW, HH, WW);
        // conv3: srcF f1(32, stride36), stride2 -> bufB(64)
        conv3x3_kernel<8, 2, 16, 4><<<dim3(7, 32, BB * 2), dim3(16, 4)>>>(
            srcF, CF, 32, w[2], bi[2], al[2], p_bufB, 64, 64, HH, WW, H2, W2);
        // conv4: bufB(64) -> srcH(64)
        conv3x3_kernel<8, 1, 32, 4><<<dim3(4, 32, BB * 2), dim3(32, 4)>>>(
            p_bufB, 64, 64, w[3], bi[3], al[3], srcH, CHh, 64, H2, W2, H2, W2);
        // conv5: srcH(64), stride2 -> bufC(96)
        conv3x3_kernel<8, 2, 16, 4><<<dim3(4, 16, BB * 3), dim3(16, 4)>>>(
            srcH, CHh, 64, w[4], bi[4], al[4], p_bufC, 96, 96, H2, W2, H4, W4);
        // conv6: bufC(96) -> srcQ(96)
        conv3x3_kernel<8, 1, 32, 4><<<dim3(2, 16, BB * 3), dim3(32, 4)>>>(
            p_bufC, 96, 96, w[5], bi[5], al[5], srcQ, CQ, 96, H4, W4, H4, W4);
    }

    // 6. forward-warp scatters (vectorized v4 reductions)
    for (int sel = 0; sel < 2; sel++) {
        const float* flF = sel ? p_f1t : p_f0t;
        const float* flH = p_fH + (size_t)sel * BB * 2 * HW2;
        const float* flQ = p_fQ + (size_t)sel * BB * 2 * HW4;
        scatter_kernel<9, CFA><<<div_up((long long)BB * HWF, 256), 256>>>(
            p_srcF + (size_t)sel * szSF, flF, p_accF + (size_t)sel * szAF, HH, WW);
        scatter_kernel<16, CHA><<<div_up((long long)BB * HW2, 256), 256>>>(
            p_srcH + (size_t)sel * szSH, flH, p_accH + (size_t)sel * szAH, H2, W2);
        scatter_kernel<24, CQA><<<div_up((long long)BB * HW4, 256), 256>>>(
            p_srcQ + (size_t)sel * szSQ, flQ, p_accQ + (size_t)sel * szAQ, H4, W4);
    }

    // 7. finalize: divide by den, transpose to NCHW output sections
    for (int sel = 0; sel < 2; sel++) {
        finalize_full<<<BB * HWF / 64, 256>>>(p_accF + (size_t)sel * szAF, out, sel);
        finalize_simple<CHh, CHA><<<BB * HW2 / 64, 256>>>(
            p_accH + (size_t)sel * szAH, out + SEC2, 128, 64 * sel, HW2);
        finalize_simple<CQ, CQA><<<BB * HW4 / 64, 256>>>(
            p_accQ + (size_t)sel * szAQ, out + SEC3, 192, 96 * sel, HW4);
    }
}

// round 3
// speedup vs baseline: 1.5603x; 1.1533x over previous
#include <cuda_runtime.h>
#include <math.h>

// ---------------------------------------------------------------------------
// Problem constants (B,3,256,448 inputs)
// ---------------------------------------------------------------------------
constexpr int BB = 4;
constexpr int HH = 256, WW = 448;
constexpr int HWF = HH * WW;                      // 114688
constexpr int H2 = 128, W2 = 224, HW2 = H2 * W2;  // 28672
constexpr int H4 = 64,  W4 = 112, HW4 = H4 * W4;  // 7168

constexpr long long N0 = (long long)BB * 6   * HWF;
constexpr long long N1 = (long long)BB * 64  * HWF;
constexpr long long N2 = (long long)BB * 128 * HW2;
constexpr long long N3 = (long long)BB * 192 * HW4;
constexpr long long SEC0 = 0;
constexpr long long SEC1 = SEC0 + N0;
constexpr long long SEC2 = SEC1 + N1;
constexpr long long SEC3 = SEC2 + N2;
constexpr long long SEC4 = SEC3 + N3;

// NHWC channel counts: src (warp source) and acc (splat accumulator, +den+pad)
constexpr int CF = 36, CFA = 40;   // full res:   [f1 32][img 3][sig 1] | +den
constexpr int CHh = 64, CHA = 68;  // half res:   f2                    | +den
constexpr int CQ = 96, CQA = 100;  // quarter:    f3                    | +den

// ---------------------------------------------------------------------------
// Device scratch (no allocations allowed -> __device__ globals)
// ---------------------------------------------------------------------------
__device__ __align__(16) float g_srcF[2][(size_t)BB * HWF * CF];
__device__ __align__(16) float g_accF[2][(size_t)BB * HWF * CFA];
__device__ __align__(16) float g_srcH[2][(size_t)BB * HW2 * CHh];
__device__ __align__(16) float g_accH[2][(size_t)BB * HW2 * CHA];
__device__ __align__(16) float g_srcQ[2][(size_t)BB * HW4 * CQ];
__device__ __align__(16) float g_accQ[2][(size_t)BB * HW4 * CQA];
__device__ __align__(16) float g_bufA[2][(size_t)BB * HWF * 32];
__device__ __align__(16) float g_bufB[2][(size_t)BB * HW2 * 64];
__device__ __align__(16) float g_bufC[2][(size_t)BB * HW4 * 96];
__device__ __align__(16) float g_flow0t[BB * 2 * HWF];
__device__ __align__(16) float g_flow1t[BB * 2 * HWF];
__device__ __align__(16) float g_flowH[2][BB * 2 * HW2];
__device__ __align__(16) float g_flowQ[2][BB * 2 * HW4];
__device__ float g_meanAcc[BB];

// ---------------------------------------------------------------------------
// Packed fp32x2 helpers (sm_100 packed FMA path)
// ---------------------------------------------------------------------------
__device__ __forceinline__ unsigned long long pack2(float v) {
    unsigned long long r;
    asm("mov.b64 %0, {%1, %1};" : "=l"(r) : "r"(__float_as_uint(v)));
    return r;
}
__device__ __forceinline__ void ffma2(unsigned long long& d,
                                      unsigned long long a, unsigned long long b) {
    asm("fma.rn.f32x2 %0, %1, %2, %0;" : "+l"(d) : "l"(a), "l"(b));
}
__device__ __forceinline__ float2 unpack2(unsigned long long v) {
    float2 f;
    asm("mov.b64 {%0, %1}, %2;" : "=f"(f.x), "=f"(f.y) : "l"(v));
    return f;
}
__device__ __forceinline__ void red4(float* p, float a, float b, float c, float d) {
    asm volatile("red.global.add.v4.f32 [%0], {%1, %2, %3, %4};"
                 :: "l"(p), "f"(a), "f"(b), "f"(c), "f"(d) : "memory");
}

// ---------------------------------------------------------------------------
// Utility kernels
// ---------------------------------------------------------------------------
__global__ void zero_kernel(float4* __restrict__ p, long long n4) {
    long long i = (long long)blockIdx.x * blockDim.x + threadIdx.x;
    if (i < n4) p[i] = make_float4(0.f, 0.f, 0.f, 0.f);
}

__global__ void zero_mean_kernel(float* __restrict__ p) {
    if (threadIdx.x < BB) p[threadIdx.x] = 0.f;
}

// stage 1: 32 blocks per batch, grid-strided float4 partial sums, atomic combine
__global__ void mean_partial_kernel(const float* __restrict__ img0,
                                    const float* __restrict__ img1,
                                    float* __restrict__ acc) {
    __shared__ float red[256];
    const int b = blockIdx.x >> 5;          // 4 batches x 32 slices
    const int slice = blockIdx.x & 31;
    const float4* p0 = reinterpret_cast<const float4*>(img0 + (size_t)b * 3 * HWF);
    const float4* p1 = reinterpret_cast<const float4*>(img1 + (size_t)b * 3 * HWF);
    const int n4 = 3 * HWF / 4;             // 86016
    float s = 0.f;
    for (int i = slice * 256 + threadIdx.x; i < n4; i += 32 * 256) {
        float4 a = p0[i], c = p1[i];
        s += (a.x + a.y) + (a.z + a.w) + (c.x + c.y) + (c.z + c.w);
    }
    red[threadIdx.x] = s;
    __syncthreads();
    for (int k = 128; k > 0; k >>= 1) {
        if (threadIdx.x < k) red[threadIdx.x] += red[threadIdx.x + k];
        __syncthreads();
    }
    if (threadIdx.x == 0) atomicAdd(acc + b, red[0]);
}

// mean-subtract images + sigma copy into srcF channels [32..35] (NHWC)
__global__ void prep_kernel(const float* __restrict__ img0,
                            const float* __restrict__ img1,
                            const float* __restrict__ sig01,
                            const float* __restrict__ sig10,
                            const float* __restrict__ mn,
                            float* __restrict__ srcF0, float* __restrict__ srcF1) {
    int id = blockIdx.x * blockDim.x + threadIdx.x;
    const int n = BB * HWF;
    if (id >= 2 * n) return;
    int sel = id >= n;
    int r = sel ? id - n : id;
    int b = r / HWF;
    int p = r - b * HWF;
    float m = mn[b] * (1.f / (6.f * HWF));
    const float* im = sel ? img1 : img0;
    const float* sg = sel ? sig10 : sig01;
    float4 v;
    v.x = im[((size_t)b * 3 + 0) * HWF + p] - m;
    v.y = im[((size_t)b * 3 + 1) * HWF + p] - m;
    v.z = im[((size_t)b * 3 + 2) * HWF + p] - m;
    v.w = sg[(size_t)b * HWF + p];
    float* dst = (sel ? srcF1 : srcF0) + ((size_t)r) * CF + 32;
    *reinterpret_cast<float4*>(dst) = v;
}

// cal_inter_flow with t = 0.5 for both directions (planar NCHW flow out)
__global__ void interflow_kernel(const float* __restrict__ flow01,
                                 const float* __restrict__ sig01,
                                 const float* __restrict__ flow10,
                                 const float* __restrict__ sig10,
                                 float* __restrict__ f0t, float* __restrict__ f1t) {
    int id = blockIdx.x * blockDim.x + threadIdx.x;
    const int n = 2 * BB * HWF;
    if (id >= n) return;
    int sel = id / (BB * HWF);
    int r = id - sel * (BB * HWF);
    int b = r / HWF;
    int p = r - b * HWF;
    const float* fl = sel ? flow10 : flow01;
    const float* sg = sel ? sig10 : sig01;
    float* dst = sel ? f1t : f0t;
    float fx = fl[((size_t)b * 2) * HWF + p];
    float fy = fl[((size_t)b * 2 + 1) * HWF + p];
    float s  = sg[(size_t)b * HWF + p];
    const float t = 0.5f;
    float ftx, fty;
    if (fabsf(s) < 0.01f) {
        ftx = t * fx;
        fty = t * fy;
    } else {
        float alpha = atan2f(fy, fx);
        float beta  = asinf(s);
        float d     = sqrtf(fx * fx + fy * fy);
        float R     = d / (2.f * s);
        const float PIH = 1.57079632679489662f;
        float th0 = alpha + PIH + beta;
        float th1 = alpha + PIH - beta;
        float tht = th0 + (th1 - th0) * t;
        ftx = R * (cosf(tht) - cosf(th0));
        fty = R * (sinf(tht) - sinf(th0));
    }
    dst[((size_t)b * 2) * HWF + p]     = ftx;
    dst[((size_t)b * 2 + 1) * HWF + p] = fty;
}

// jax.image.resize(bilinear, antialias=True) exact-factor downsample + 1/f scale
__global__ void downflow_kernel(const float* __restrict__ fl, float* __restrict__ o,
                                int f, int ho, int wo) {
    const int hw = ho * wo;
    const int n = BB * 2 * hw;
    int id = blockIdx.x * blockDim.x + threadIdx.x;
    if (id >= n) return;
    int p = id % hw;
    int c = (id / hw) & 1;
    int b = id / (2 * hw);
    int oy = p / wo, ox = p % wo;
    float invf = 1.f / f;
    float sy = f * oy + (f - 1) * 0.5f;
    float sx = f * ox + (f - 1) * 0.5f;
    float wy[8], wxv[8];
    int jys[8], jxs[8];
    int ny = 0, nx = 0;
    float sumy = 0.f, sumx = 0.f;
    int jy0 = (int)floorf(sy) - f + 1;
    int jx0 = (int)floorf(sx) - f + 1;
    for (int k = 0; k < 2 * f; k++) {
        int jy = jy0 + k;
        float wv = 1.f - fabsf(jy - sy) * invf;
        if (jy >= 0 && jy < HH && wv > 0.f) { wy[ny] = wv; jys[ny] = jy; ny++; sumy += wv; }
        int jx = jx0 + k;
        wv = 1.f - fabsf(jx - sx) * invf;
        if (jx >= 0 && jx < WW && wv > 0.f) { wxv[nx] = wv; jxs[nx] = jx; nx++; sumx += wv; }
    }
    const float* ip = fl + ((size_t)b * 2 + c) * HWF;
    float acc = 0.f;
    for (int iy = 0; iy < ny; iy++) {
        const float* rp = ip + jys[iy] * WW;
        float rowacc = 0.f;
        for (int ix = 0; ix < nx; ix++) rowacc += wxv[ix] * rp[jxs[ix]];
        acc += wy[iy] * rowacc;
    }
    o[id] = acc / (sumy * sumx) * invf;
}

// ---------------------------------------------------------------------------
// 3x3 conv + bias + PReLU, NHWC in/out, packed f32x2 FMA, PX pixels/thread.
// Each thread: 32 output channels x PX pixels. Batched over blockIdx.z.
// ---------------------------------------------------------------------------
template<int CINC, int STRIDE, int TW, int TH, int PX>
__global__ __launch_bounds__(TW * TH)
void conv3x3_kernel(const float* __restrict__ in, int CinStr, int Cin,
                    const float* __restrict__ wgt, const float* __restrict__ bias,
                    const float* __restrict__ alpha,
                    float* __restrict__ out, int CoutStr, int Cout,
                    int Hin, int Win, int Hout, int Wout) {
    constexpr int OW = PX * TW;
    constexpr int IW = OW * STRIDE + 2;
    constexpr int IH = TH * STRIDE + 2;
    constexpr int NT = TW * TH;
    constexpr int IHW = IH * IW;
    __shared__ float s_in[CINC * IHW];
    __shared__ __align__(16) float s_w[CINC * 9 * 32];

    const int tx = threadIdx.x, ty = threadIdx.y;
    const int tid = ty * TW + tx;
    const int nCo = Cout >> 5;
    const int b   = blockIdx.z / nCo;        // batch spans 2*BB images
    const int co0 = (blockIdx.z % nCo) << 5;
    const int ox0 = blockIdx.x * OW;
    const int oy0 = blockIdx.y * TH;
    const int ix0 = ox0 * STRIDE - 1;
    const int iy0 = oy0 * STRIDE - 1;

    const float* inB = in + (size_t)b * Hin * Win * CinStr;

    unsigned long long acc[PX][16];
#pragma unroll
    for (int px = 0; px < PX; px++)
#pragma unroll
        for (int i = 0; i < 16; i++) acc[px][i] = 0ull;

    for (int cc = 0; cc < Cin; cc += CINC) {
        __syncthreads();
        if constexpr (CINC % 4 == 0) {
            constexpr int Q = CINC / 4;
            for (int idx = tid; idx < IHW * Q; idx += NT) {
                int pix = idx / Q, q = idx - (idx / Q) * Q;
                int iy = pix / IW, ix = pix - iy * IW;
                int gy = iy0 + iy, gx = ix0 + ix;
                float4 v = make_float4(0.f, 0.f, 0.f, 0.f);
                if ((unsigned)gy < (unsigned)Hin && (unsigned)gx < (unsigned)Win)
                    v = *reinterpret_cast<const float4*>(
                        inB + ((size_t)gy * Win + gx) * CinStr + cc + 4 * q);
                s_in[(4 * q + 0) * IHW + pix] = v.x;
                s_in[(4 * q + 1) * IHW + pix] = v.y;
                s_in[(4 * q + 2) * IHW + pix] = v.z;
                s_in[(4 * q + 3) * IHW + pix] = v.w;
            }
        } else {
            for (int idx = tid; idx < CINC * IHW; idx += NT) {
                int ci = idx / IHW;
                int pix = idx - ci * IHW;
                int iy = pix / IW, ix = pix - iy * IW;
                int gy = iy0 + iy, gx = ix0 + ix;
                float v = 0.f;
                if ((unsigned)gy < (unsigned)Hin && (unsigned)gx < (unsigned)Win)
                    v = inB[((size_t)gy * Win + gx) * CinStr + cc + ci];
                s_in[idx] = v;
            }
        }
        for (int idx = tid; idx < CINC * 9 * 32; idx += NT) {
            int co  = idx & 31;
            int rt  = idx >> 5;
            int ci  = rt / 9;
            int tap = rt - ci * 9;
            s_w[(ci * 9 + tap) * 32 + co] =
                wgt[((size_t)(co0 + co) * Cin + cc + ci) * 9 + tap];
        }
        __syncthreads();

        for (int ci = 0; ci < CINC; ci++) {
            const float* bi = s_in + ci * IHW;
#pragma unroll
            for (int ky = 0; ky < 3; ky++) {
#pragma unroll
                for (int kx = 0; kx < 3; kx++) {
                    unsigned long long vv[PX];
#pragma unroll
                    for (int px = 0; px < PX; px++)
                        vv[px] = pack2(bi[(ty * STRIDE + ky) * IW +
                                          (tx + px * TW) * STRIDE + kx]);
                    const ulonglong2* wp = reinterpret_cast<const ulonglong2*>(
                        s_w + (ci * 9 + ky * 3 + kx) * 32);
#pragma unroll
                    for (int j = 0; j < 8; j++) {
                        ulonglong2 w2 = wp[j];
#pragma unroll
                        for (int px = 0; px < PX; px++) {
                            ffma2(acc[px][2 * j],     vv[px], w2.x);
                            ffma2(acc[px][2 * j + 1], vv[px], w2.y);
                        }
                    }
                }
            }
        }
    }

    const float al = __ldg(alpha);
    const int oy = oy0 + ty;
#pragma unroll
    for (int px = 0; px < PX; px++) {
        const int ox = ox0 + tx + px * TW;
        if (ox < Wout && oy < Hout) {
            float* op = out + ((size_t)b * Hout * Wout + (size_t)oy * Wout + ox) * CoutStr + co0;
#pragma unroll
            for (int j = 0; j < 8; j++) {
                float2 p0 = unpack2(acc[px][2 * j]);
                float2 p1 = unpack2(acc[px][2 * j + 1]);
                float4 o4;
                float r;
                r = p0.x + __ldg(bias + co0 + 4 * j + 0); o4.x = r > 0.f ? r : al * r;
                r = p0.y + __ldg(bias + co0 + 4 * j + 1); o4.y = r > 0.f ? r : al * r;
                r = p1.x + __ldg(bias + co0 + 4 * j + 2); o4.z = r > 0.f ? r : al * r;
                r = p1.y + __ldg(bias + co0 + 4 * j + 3); o4.w = r > 0.f ? r : al * r;
                reinterpret_cast<float4*>(op)[j] = o4;
            }
        }
    }
}

// ---------------------------------------------------------------------------
// Forward-warp scatter: NHWC src, NHWC acc (den at channel C), v4 reductions.
// ---------------------------------------------------------------------------
template<int C4, int CA>
__global__ void scatter_kernel(const float* __restrict__ src,
                               const float* __restrict__ flow,
                               float* __restrict__ acc, int Hs, int Ws) {
    constexpr int C = 4 * C4;
    const int HWs = Hs * Ws;
    int id = blockIdx.x * blockDim.x + threadIdx.x;
    if (id >= BB * HWs) return;
    int b = id / HWs;
    int p = id - b * HWs;
    int y = p / Ws;
    int x = p - y * Ws;
    const float* fb = flow + (size_t)b * 2 * HWs;
    float fx = fb[p], fy = fb[HWs + p];
    float txf = x + fx, tyf = y + fy;
    float x0f = floorf(txf), y0f = floorf(tyf);
    float dx = txf - x0f, dy = tyf - y0f;
    int x0 = (int)x0f, y0 = (int)y0f;
    float w[4] = { (1.f - dx) * (1.f - dy), dx * (1.f - dy),
                   (1.f - dx) * dy,         dx * dy };
    int xs[4] = { x0, x0 + 1, x0, x0 + 1 };
    int ys[4] = { y0, y0, y0 + 1, y0 + 1 };
    int idxs[4];
    bool ok[4];
#pragma unroll
    for (int k = 0; k < 4; k++) {
        ok[k] = xs[k] >= 0 && xs[k] < Ws && ys[k] >= 0 && ys[k] < Hs && w[k] > 0.f;
        idxs[k] = ys[k] * Ws + xs[k];
    }
    float* accB = acc + (size_t)b * HWs * CA;
    const float4* sp = reinterpret_cast<const float4*>(src + (size_t)id * C);
#pragma unroll
    for (int c4 = 0; c4 < C4; c4++) {
        float4 v = sp[c4];
#pragma unroll
        for (int k = 0; k < 4; k++) {
            if (ok[k])
                red4(accB + (size_t)idxs[k] * CA + 4 * c4,
                     v.x * w[k], v.y * w[k], v.z * w[k], v.w * w[k]);
        }
    }
#pragma unroll
    for (int k = 0; k < 4; k++)
        if (ok[k]) atomicAdd(accB + (size_t)idxs[k] * CA + C, w[k]);
}

// ---------------------------------------------------------------------------
// Finalize: NHWC acc -> divide by den -> NCHW output sections
// ---------------------------------------------------------------------------
template<int C, int CA>
__global__ void finalize_simple(const float* __restrict__ acc,
                                float* __restrict__ outsec,
                                int Ctot, int coff, int HWs) {
    __shared__ float s[64 * (CA + 1)];
    __shared__ float inv[64];
    const int base = blockIdx.x * 64;
    const int tid = threadIdx.x;
    constexpr int Q = CA / 4;
    for (int idx = tid; idx < 64 * Q; idx += 256) {
        int p = idx / Q, q = idx - (idx / Q) * Q;
        float4 v = *reinterpret_cast<const float4*>(acc + ((size_t)(base + p)) * CA + 4 * q);
        s[p * (CA + 1) + 4 * q + 0] = v.x;
        s[p * (CA + 1) + 4 * q + 1] = v.y;
        s[p * (CA + 1) + 4 * q + 2] = v.z;
        s[p * (CA + 1) + 4 * q + 3] = v.w;
    }
    __syncthreads();
    if (tid < 64) inv[tid] = 1.f / fmaxf(s[tid * (CA + 1) + C], 1e-7f);
    __syncthreads();
    const int b = base / HWs;
    const int p0 = base - b * HWs;
    for (int id = tid; id < C * 64; id += 256) {
        int c = id >> 6, i = id & 63;
        outsec[((size_t)(b * Ctot + coff + c)) * HWs + p0 + i] = s[i * (CA + 1) + c] * inv[i];
    }
}

// full-res: channels 0-31 -> SEC1(feat), 32-34 -> SEC0(img), 35 -> SEC4(sig)
__global__ void finalize_full(const float* __restrict__ acc,
                              float* __restrict__ out, int sel) {
    __shared__ float s[64 * 41];
    __shared__ float inv[64];
    const int base = blockIdx.x * 64;
    const int tid = threadIdx.x;
    for (int idx = tid; idx < 64 * 10; idx += 256) {
        int p = idx / 10, q = idx - (idx / 10) * 10;
        float4 v = *reinterpret_cast<const float4*>(acc + ((size_t)(base + p)) * CFA + 4 * q);
        s[p * 41 + 4 * q + 0] = v.x;
        s[p * 41 + 4 * q + 1] = v.y;
        s[p * 41 + 4 * q + 2] = v.z;
        s[p * 41 + 4 * q + 3] = v.w;
    }
    __syncthreads();
    if (tid < 64) inv[tid] = 1.f / fmaxf(s[tid * 41 + 36], 1e-7f);
    __syncthreads();
    const int b = base / HWF;
    const int p0 = base - b * HWF;
    for (int id = tid; id < 36 * 64; id += 256) {
        int c = id >> 6, i = id & 63;
        float val = s[i * 41 + c] * inv[i];
        size_t dst;
        if (c < 32)       dst = SEC1 + ((size_t)(b * 64 + 32 * sel + c)) * HWF + p0 + i;
        else if (c < 35)  dst = SEC0 + ((size_t)(b * 6 + 3 * sel + (c - 32))) * HWF + p0 + i;
        else              dst = SEC4 + ((size_t)(b * 2 + sel)) * HWF + p0 + i;
        out[dst] = val;
    }
}

// ---------------------------------------------------------------------------
// Host launcher
// ---------------------------------------------------------------------------
static inline int div_up(long long a, int b) { return (int)((a + b - 1) / b); }

extern "C" void kernel_launch(void* const* d_in, const int* in_sizes, int n_in,
                              void* d_out, int out_size) {
    const float* img0    = (const float*)d_in[0];
    const float* img1    = (const float*)d_in[1];
    const float* flow01  = (const float*)d_in[2];
    const float* sigma01 = (const float*)d_in[3];
    const float* flow10  = (const float*)d_in[4];
    const float* sigma10 = (const float*)d_in[5];
    const float *w[6], *bi[6], *al[6];
    for (int i = 0; i < 6; i++) {
        w[i]  = (const float*)d_in[6 + 3 * i];
        bi[i] = (const float*)d_in[7 + 3 * i];
        al[i] = (const float*)d_in[8 + 3 * i];
    }
    float* out = (float*)d_out;

    float *p_srcF, *p_accF, *p_srcH, *p_accH, *p_srcQ, *p_accQ;
    float *p_bufA, *p_bufB, *p_bufC, *p_f0t, *p_f1t, *p_fH, *p_fQ, *p_mean;
    cudaGetSymbolAddress((void**)&p_srcF, g_srcF);
    cudaGetSymbolAddress((void**)&p_accF, g_accF);
    cudaGetSymbolAddress((void**)&p_srcH, g_srcH);
    cudaGetSymbolAddress((void**)&p_accH, g_accH);
    cudaGetSymbolAddress((void**)&p_srcQ, g_srcQ);
    cudaGetSymbolAddress((void**)&p_accQ, g_accQ);
    cudaGetSymbolAddress((void**)&p_bufA, g_bufA);
    cudaGetSymbolAddress((void**)&p_bufB, g_bufB);
    cudaGetSymbolAddress((void**)&p_bufC, g_bufC);
    cudaGetSymbolAddress((void**)&p_f0t,  g_flow0t);
    cudaGetSymbolAddress((void**)&p_f1t,  g_flow1t);
    cudaGetSymbolAddress((void**)&p_fH,   g_flowH);
    cudaGetSymbolAddress((void**)&p_fQ,   g_flowQ);
    cudaGetSymbolAddress((void**)&p_mean, g_meanAcc);

    const size_t szSF = (size_t)BB * HWF * CF;
    const size_t szAF = (size_t)BB * HWF * CFA;
    const size_t szSH = (size_t)BB * HW2 * CHh;
    const size_t szAH = (size_t)BB * HW2 * CHA;
    const size_t szSQ = (size_t)BB * HW4 * CQ;
    const size_t szAQ = (size_t)BB * HW4 * CQA;

    // 1. zero accumulators + mean acc
    zero_kernel<<<div_up(2LL * szAF / 4, 256), 256>>>((float4*)p_accF, 2LL * szAF / 4);
    zero_kernel<<<div_up(2LL * szAH / 4, 256), 256>>>((float4*)p_accH, 2LL * szAH / 4);
    zero_kernel<<<div_up(2LL * szAQ / 4, 256), 256>>>((float4*)p_accQ, 2LL * szAQ / 4);
    zero_mean_kernel<<<1, 32>>>(p_mean);

    // 2. mean (two-stage) + mean-center images + pack img/sig into srcF ch 32..35
    mean_partial_kernel<<<BB * 32, 256>>>(img0, img1, p_mean);
    prep_kernel<<<div_up(2LL * BB * HWF, 256), 256>>>(img0, img1, sigma01, sigma10,
                                                      p_mean, p_srcF, p_srcF + szSF);

    // 3. intermediate flows (t = 0.5 both directions)
    interflow_kernel<<<div_up(2LL * BB * HWF, 256), 256>>>(flow01, sigma01,
                                                           flow10, sigma10,
                                                           p_f0t, p_f1t);

    // 4. antialiased downsampled flows
    downflow_kernel<<<div_up((long long)BB * 2 * HW2, 256), 256>>>(p_f0t, p_fH, 2, H2, W2);
    downflow_kernel<<<div_up((long long)BB * 2 * HW2, 256), 256>>>(p_f1t, p_fH + (size_t)BB * 2 * HW2, 2, H2, W2);
    downflow_kernel<<<div_up((long long)BB * 2 * HW4, 256), 256>>>(p_f0t, p_fQ, 4, H4, W4);
    downflow_kernel<<<div_up((long long)BB * 2 * HW4, 256), 256>>>(p_f1t, p_fQ + (size_t)BB * 2 * HW4, 4, H4, W4);

    // 5. feature extractor (NHWC), both images batched in blockIdx.z (8 images)
    // conv1: img(3, stride36 @ch32) -> bufA(32)      PX=4, 64-wide tiles
    conv3x3_kernel<3, 1, 16, 4, 4><<<dim3(7, 64, 8), dim3(16, 4)>>>(
        p_srcF + 32, CF, 3, w[0], bi[0], al[0], p_bufA, 32, 32, HH, WW, HH, WW);
    // conv2: bufA(32) -> srcF ch0..31 (stride 36)
    conv3x3_kernel<8, 1, 16, 4, 4><<<dim3(7, 64, 8), dim3(16, 4)>>>(
        p_bufA, 32, 32, w[1], bi[1], al[1], p_srcF, CF, 32, HH, WW, HH, WW);
    // conv3: srcF f1(32, stride36), stride2 -> bufB(64)   PX=2
    conv3x3_kernel<8, 2, 16, 4, 2><<<dim3(7, 32, 16), dim3(16, 4)>>>(
        p_srcF, CF, 32, w[2], bi[2], al[2], p_bufB, 64, 64, HH, WW, H2, W2);
    // conv4: bufB(64) -> srcH(64)
    conv3x3_kernel<8, 1, 16, 4, 4><<<dim3(4, 32, 16), dim3(16, 4)>>>(
        p_bufB, 64, 64, w[3], bi[3], al[3], p_srcH, CHh, 64, H2, W2, H2, W2);
    // conv5: srcH(64), stride2 -> bufC(96)   PX=2
    conv3x3_kernel<8, 2, 16, 4, 2><<<dim3(4, 16, 24), dim3(16, 4)>>>(
        p_srcH, CHh, 64, w[4], bi[4], al[4], p_bufC, 96, 96, H2, W2, H4, W4);
    // conv6: bufC(96) -> srcQ(96)
    conv3x3_kernel<8, 1, 16, 4, 4><<<dim3(2, 16, 24), dim3(16, 4)>>>(
        p_bufC, 96, 96, w[5], bi[5], al[5], p_srcQ, CQ, 96, H4, W4, H4, W4);

    // 6. forward-warp scatters (vectorized v4 reductions)
    for (int sel = 0; sel < 2; sel++) {
        const float* flF = sel ? p_f1t : p_f0t;
        const float* flH = p_fH + (size_t)sel * BB * 2 * HW2;
        const float* flQ = p_fQ + (size_t)sel * BB * 2 * HW4;
        scatter_kernel<9, CFA><<<div_up((long long)BB * HWF, 256), 256>>>(
            p_srcF + (size_t)sel * szSF, flF, p_accF + (size_t)sel * szAF, HH, WW);
        scatter_kernel<16, CHA><<<div_up((long long)BB * HW2, 256), 256>>>(
            p_srcH + (size_t)sel * szSH, flH, p_accH + (size_t)sel * szAH, H2, W2);
        scatter_kernel<24, CQA><<<div_up((long long)BB * HW4, 256), 256>>>(
            p_srcQ + (size_t)sel * szSQ, flQ, p_accQ + (size_t)sel * szAQ, H4, W4);
    }

    // 7. finalize: divide by den, transpose to NCHW output sections
    for (int sel = 0; sel < 2; sel++) {
        finalize_full<<<BB * HWF / 64, 256>>>(p_accF + (size_t)sel * szAF, out, sel);
        finalize_simple<CHh, CHA><<<BB * HW2 / 64, 256>>>(
            p_accH + (size_t)sel * szAH, out + SEC2, 128, 64 * sel, HW2);
        finalize_simple<CQ, CQA><<<BB * HW4 / 64, 256>>>(
            p_accQ + (size_t)sel * szAQ, out + SEC3, 192, 96 * sel, HW4);
    }
}